// round 13
// baseline (speedup 1.0000x reference)
#include <cuda_runtime.h>
#include <cuda_fp16.h>
#include <math.h>
#include <stdint.h>

#define TT     64
#define BBATCH 1024
#define DET    512
#define STO    64
#define EMBD   1024
#define ACTD   6
#define MLPD   512
#define COUT   896

// ---------------- persistent scratch ----------------------------------------
__device__ __align__(16) __half g_Wi16 [512 * 128];
__device__ __align__(16) __half g_Wg16 [2 * 1536 * 512];   // gate-interleaved W_ih|W_hh
__device__ __align__(16) __half g_Wp116[512 * 512];
__device__ __align__(16) __half g_Wq116[512 * 1536];
__device__ __align__(16) __half g_Wp216[128 * 512];
__device__ __align__(16) __half g_Wq216[128 * 512];
__device__ __align__(16) __half g_x16  [BBATCH * 512];
__device__ __align__(16) __half g_det16[BBATCH * 512];
__device__ __align__(16) __half g_emb16[BBATCH * EMBD];
__device__ __align__(16) __half g_p116 [BBATCH * 512];
__device__ __align__(16) __half g_q116 [BBATCH * 512];
__device__ __align__(16) float  g_deter[2 * BBATCH * 512];
__device__ __align__(16) float  g_stoc [2 * BBATCH * 64];

// ---------------- math ------------------------------------------------------
__device__ __forceinline__ float eluf(float x)  { return x > 0.f ? x : expm1f(x); }
__device__ __forceinline__ float sigm(float x)  { return 1.f / (1.f + expf(-x)); }
__device__ __forceinline__ float softp(float x) { return x > 0.f ? x + log1pf(expf(-x)) : log1pf(expf(x)); }

// ---------------- PTX primitives ---------------------------------------------
__device__ __forceinline__ uint32_t s2u(const void* p) {
    uint32_t a;
    asm("{ .reg .u64 t; cvta.to.shared.u64 t, %1; cvt.u32.u64 %0, t; }" : "=r"(a) : "l"(p));
    return a;
}
#define CPA16(d, s) asm volatile("cp.async.cg.shared.global [%0], [%1], 16;" :: "r"(d), "l"(s))
#define CPC()       asm volatile("cp.async.commit_group;" ::: "memory")
#define CPW(n)      asm volatile("cp.async.wait_group %0;" :: "n"(n) : "memory")

__device__ __forceinline__ void ldm_x4(uint32_t* r, const void* p) {
    uint32_t a = s2u(p);
    asm volatile("ldmatrix.sync.aligned.m8n8.x4.shared.b16 {%0,%1,%2,%3}, [%4];"
                 : "=r"(r[0]), "=r"(r[1]), "=r"(r[2]), "=r"(r[3]) : "r"(a));
}
__device__ __forceinline__ void ldm_x2(uint32_t* r, const void* p) {
    uint32_t a = s2u(p);
    asm volatile("ldmatrix.sync.aligned.m8n8.x2.shared.b16 {%0,%1}, [%2];"
                 : "=r"(r[0]), "=r"(r[1]) : "r"(a));
}
__device__ __forceinline__ void mma16816(float* c, const uint32_t* a, const uint32_t* b) {
    asm volatile(
        "mma.sync.aligned.m16n8k16.row.col.f32.f16.f16.f32 "
        "{%0,%1,%2,%3}, {%4,%5,%6,%7}, {%8,%9}, {%0,%1,%2,%3};"
        : "+f"(c[0]), "+f"(c[1]), "+f"(c[2]), "+f"(c[3])
        : "r"(a[0]), "r"(a[1]), "r"(a[2]), "r"(a[3]), "r"(b[0]), "r"(b[1]));
}

// ---------------- prep kernels ----------------------------------------------
__global__ __launch_bounds__(256) void k_prep(
    const float* __restrict__ src, __half* __restrict__ dst,
    int total, int srcK, int dstK, int srcN, int trans)
{
    for (int idx = blockIdx.x * 256 + threadIdx.x; idx < total; idx += gridDim.x * 256) {
        int n = idx / dstK, k = idx % dstK;
        float v = 0.f;
        if (k < srcK)
            v = trans ? src[(size_t)k * srcN + n] : src[(size_t)n * srcK + k];
        dst[idx] = __float2half(v);
    }
}

__global__ __launch_bounds__(256) void k_prep_gru(
    const float* __restrict__ Wih, const float* __restrict__ Whh,
    __half* __restrict__ dst)
{
    int total = 1536 * 512;
    for (int idx = blockIdx.x * 256 + threadIdx.x; idx < total; idx += gridDim.x * 256) {
        int rr = idx / 512, k = idx % 512;
        int jb = rr / 192, rem = rr % 192;
        int gate = rem >> 6, jj = rem & 63;
        int srow = gate * 512 + jb * 64 + jj;
        dst[idx]         = __float2half(Wih[(size_t)srow * 512 + k]);
        dst[total + idx] = __float2half(Whh[(size_t)srow * 512 + k]);
    }
}

// ---------------- step kernels ----------------------------------------------

// K1: x16 = fp16(ELU(cat(stoc*nt, act) @ Wi + bi)) + emb fp16 convert.
// grid(8,16). 64-row x 64-col tiles; K=70 padded to 128 (2 chunks of 64).
__global__ __launch_bounds__(256) void kg_x(
    const float* __restrict__ stoc_in, const float* __restrict__ act_t,
    const float* __restrict__ nt, const float* __restrict__ bi,
    const float* __restrict__ emb_t)
{
    __shared__ __align__(16) __half sA[64][72];
    __shared__ __align__(16) __half sB[64][72];
    const int tid = threadIdx.x, lane = tid & 31, w = tid >> 5;
    const int wm16 = (w & 3) * 16, nc = (w >> 2) * 32;
    int rowBase = blockIdx.y * 64, colBase = blockIdx.x * 64;
    float c[16];
#pragma unroll
    for (int i = 0; i < 16; i++) c[i] = 0.f;
    uint32_t sBu = s2u(&sB[0][0]);

    for (int ch = 0; ch < 2; ch++) {
        int k0 = ch * 64;
        // B tiles via cp.async (g_Wi16 zero-padded to 128 k)
#pragma unroll
        for (int i = 0; i < 2; i++) {
            int ww = tid + i * 256;
            int row = ww >> 3, seg = ww & 7;
            CPA16(sBu + row * 144 + seg * 16,
                  (const char*)(g_Wi16 + (size_t)(colBase + row) * 128 + k0) + seg * 16);
        }
        CPC();
        // A tiles manual (input concat)
#pragma unroll
        for (int i = 0; i < 8; i++) {
            int ww = tid + i * 256;
            int row = ww >> 5, kp = ww & 31;
            int b = rowBase + row, k = k0 + kp * 2;
            float s = nt[b];
            float lo = (k < STO) ? stoc_in[b * STO + k] * s
                     : ((k < STO + ACTD) ? act_t[b * ACTD + (k - STO)] : 0.f);
            int k1 = k + 1;
            float hi = (k1 < STO) ? stoc_in[b * STO + k1] * s
                     : ((k1 < STO + ACTD) ? act_t[b * ACTD + (k1 - STO)] : 0.f);
            __half2 v = __floats2half2_rn(lo, hi);
            *(uint32_t*)&sA[row][kp * 2] = *(uint32_t*)&v;
        }
        CPW(0);
        __syncthreads();
#pragma unroll
        for (int kk = 0; kk < 4; kk++) {
            int kb = kk * 16;
            uint32_t afr[4];
            ldm_x4(afr, &sA[wm16 + (lane & 15)][kb + ((lane >> 4) << 3)]);
            uint32_t bfr[4][2];
#pragma unroll
            for (int nt2 = 0; nt2 < 4; nt2++)
                ldm_x2(bfr[nt2], &sB[nc + nt2 * 8 + (lane & 7)][kb + (((lane >> 3) & 1) << 3)]);
#pragma unroll
            for (int nt2 = 0; nt2 < 4; nt2++)
                mma16816(c + nt2 * 4, afr, bfr[nt2]);
        }
        __syncthreads();
    }
    // epilogue
#pragma unroll
    for (int nt2 = 0; nt2 < 4; nt2++) {
        int col = colBase + nc + nt2 * 8 + (lane & 3) * 2;
#pragma unroll
        for (int h = 0; h < 2; h++) {
            int b = rowBase + wm16 + (lane >> 2) + h * 8;
            float v0 = eluf(c[nt2 * 4 + h * 2]     + bi[col]);
            float v1 = eluf(c[nt2 * 4 + h * 2 + 1] + bi[col + 1]);
            *(__half2*)(g_x16 + (size_t)b * 512 + col) = __floats2half2_rn(v0, v1);
        }
    }
    // emb conversion: CTA (0..127) converts 8192 floats
    {
        int cta = blockIdx.y * 8 + blockIdx.x;
        const float4* src = (const float4*)emb_t;
#pragma unroll
        for (int i = 0; i < 8; i++) {
            int idx4 = cta * 2048 + i * 256 + tid;
            float4 f = src[idx4];
            __half2 h0 = __floats2half2_rn(f.x, f.y);
            __half2 h1 = __floats2half2_rn(f.z, f.w);
            uint2 pk = make_uint2(*(uint32_t*)&h0, *(uint32_t*)&h1);
            *(uint2*)(g_emb16 + (size_t)idx4 * 4) = pk;
        }
    }
}

// K2: fused GRU. grid(8,16). 64-row x 192-col (3 gates x 64 j) tiles.
// 16 chunks of 32 k. 3-stage cp.async pipeline, 1 sync per chunk.
// stage layout (40960B): sAx@0 (64x40h), sAh@5120, sBi@10240 (192x40h), sBh@25600
__global__ __launch_bounds__(256) void kg_gruf(
    const float* __restrict__ deter_in, const float* __restrict__ nt,
    const float* __restrict__ b_ih, const float* __restrict__ b_hh,
    float* __restrict__ deter_out, float* __restrict__ out_t)
{
    extern __shared__ __align__(16) unsigned char raw[];
    const int tid = threadIdx.x, lane = tid & 31, w = tid >> 5;
    const int wm16 = (w & 3) * 16, wn = w >> 2;          // wn in {0,1}: 96 cols
    const int rowBase = blockIdx.y * 64;
    const int cb192 = blockIdx.x * 192;
    const int jb64  = blockIdx.x * 64;
    const uint32_t sbase = s2u(raw);

    float cgi[48], cgh[48];
#pragma unroll
    for (int i = 0; i < 48; i++) { cgi[i] = 0.f; cgh[i] = 0.f; }

    const __half* Bih = g_Wg16;
    const __half* Bhh = g_Wg16 + 1536 * 512;

#define GRU_ISSUE(cc, s) do { \
        int k0 = (cc) * 32; \
        uint32_t st = sbase + (s) * 40960; \
        { int row = tid >> 2, seg = tid & 3; \
          CPA16(st + row * 80 + seg * 16, \
                (const char*)(g_x16 + (size_t)(rowBase + row) * 512 + k0) + seg * 16); } \
        _Pragma("unroll") \
        for (int i = 0; i < 3; i++) { \
            int ww = tid + i * 256; \
            int row = ww >> 2, seg = ww & 3; \
            CPA16(st + 10240 + row * 80 + seg * 16, \
                  (const char*)(Bih + (size_t)(cb192 + row) * 512 + k0) + seg * 16); \
            CPA16(st + 25600 + row * 80 + seg * 16, \
                  (const char*)(Bhh + (size_t)(cb192 + row) * 512 + k0) + seg * 16); \
        } \
        CPC(); \
    } while (0)

    uint32_t pAh[4];
#define GRU_MLOAD(cc) do { \
        int k0 = (cc) * 32; \
        _Pragma("unroll") \
        for (int i = 0; i < 4; i++) { \
            int ww = tid + i * 256; \
            int row = ww >> 4, kp = ww & 15; \
            int b = rowBase + row, k = k0 + kp * 2; \
            float2 f = *(const float2*)(deter_in + (size_t)b * 512 + k); \
            float s = nt[b]; \
            __half2 v = __floats2half2_rn(f.x * s, f.y * s); \
            pAh[i] = *(uint32_t*)&v; \
        } \
    } while (0)

    GRU_ISSUE(0, 0);
    GRU_ISSUE(1, 1);
    GRU_MLOAD(0);

    for (int c = 0; c < 16; c++) {
        int s = c % 3;
        if (c + 1 < 16) { CPW(1); } else { CPW(0); }
        // manual A_h store for chunk c
#pragma unroll
        for (int i = 0; i < 4; i++) {
            int ww = tid + i * 256;
            int row = ww >> 4, kp = ww & 15;
            *(uint32_t*)(raw + s * 40960 + 5120 + row * 80 + kp * 4) = pAh[i];
        }
        __syncthreads();
        if (c + 2 < 16) GRU_ISSUE(c + 2, (c + 2) % 3);
        if (c + 1 < 16) GRU_MLOAD(c + 1);

        __half (*sAx)[40] = (__half(*)[40])(raw + s * 40960);
        __half (*sAh)[40] = (__half(*)[40])(raw + s * 40960 + 5120);
        __half (*sBi)[40] = (__half(*)[40])(raw + s * 40960 + 10240);
        __half (*sBh)[40] = (__half(*)[40])(raw + s * 40960 + 25600);
#pragma unroll
        for (int kk = 0; kk < 2; kk++) {
            int kb = kk * 16;
            uint32_t afx[4], afh[4];
            ldm_x4(afx, &sAx[wm16 + (lane & 15)][kb + ((lane >> 4) << 3)]);
            ldm_x4(afh, &sAh[wm16 + (lane & 15)][kb + ((lane >> 4) << 3)]);
#pragma unroll
            for (int nt2 = 0; nt2 < 12; nt2++) {
                uint32_t bf[2];
                ldm_x2(bf, &sBi[wn * 96 + nt2 * 8 + (lane & 7)][kb + (((lane >> 3) & 1) << 3)]);
                mma16816(cgi + nt2 * 4, afx, bf);
                ldm_x2(bf, &sBh[wn * 96 + nt2 * 8 + (lane & 7)][kb + (((lane >> 3) & 1) << 3)]);
                mma16816(cgh + nt2 * 4, afh, bf);
            }
        }
    }
    __syncthreads();

    // ---- gate epilogue (r,z exchanged via smem overlay) ----
    float (*rS)[65] = (float(*)[65])(raw);
    float (*zS)[65] = (float(*)[65])(raw + 64 * 65 * 4);

#pragma unroll
    for (int nt2 = 0; nt2 < 12; nt2++) {
#pragma unroll
        for (int h = 0; h < 2; h++) {
            int row = wm16 + (lane >> 2) + h * 8;
#pragma unroll
            for (int q = 0; q < 2; q++) {
                int col = wn * 96 + nt2 * 8 + (lane & 3) * 2 + q;
                int gate = col >> 6, jj = col & 63;
                int j = jb64 + jj;
                float gi = cgi[nt2 * 4 + h * 2 + q];
                float gh = cgh[nt2 * 4 + h * 2 + q];
                if (gate == 0)
                    rS[row][jj] = sigm(gi + gh + b_ih[j] + b_hh[j]);
                else if (gate == 1)
                    zS[row][jj] = sigm(gi + gh + b_ih[512 + j] + b_hh[512 + j]);
            }
        }
    }
    __syncthreads();
#pragma unroll
    for (int nt2 = 0; nt2 < 12; nt2++) {
#pragma unroll
        for (int h = 0; h < 2; h++) {
            int row = wm16 + (lane >> 2) + h * 8;
            int b = rowBase + row;
#pragma unroll
            for (int q = 0; q < 2; q++) {
                int col = wn * 96 + nt2 * 8 + (lane & 3) * 2 + q;
                int gate = col >> 6, jj = col & 63;
                if (gate == 2) {
                    int j = jb64 + jj;
                    float inn = cgi[nt2 * 4 + h * 2 + q] + b_ih[1024 + j];
                    float hn  = cgh[nt2 * 4 + h * 2 + q] + b_hh[1024 + j];
                    float r = rS[row][jj];
                    float z = zS[row][jj];
                    float n = tanhf(inn + r * hn);
                    float hv = deter_in[(size_t)b * DET + j] * nt[b];
                    float dn = (1.f - z) * n + z * hv;
                    deter_out[(size_t)b * DET + j] = dn;
                    g_det16[(size_t)b * 512 + j] = __float2half(dn);
                    out_t[(size_t)b * COUT + j] = dn;
                }
            }
        }
    }
}

// K3: mid layers. grid(8,16,2). 64x64 tiles, chunks of 64 k, 3-stage cp.async.
// stage (18432B): sA@0 (64x72h), sB@9216 (64x72h).
__global__ __launch_bounds__(256) void kg_mid(
    const float* __restrict__ bp1, const float* __restrict__ bq1)
{
    extern __shared__ __align__(16) unsigned char raw[];
    const int tid = threadIdx.x, lane = tid & 31, w = tid >> 5;
    const int wm16 = (w & 3) * 16, nc = (w >> 2) * 32;
    int z = blockIdx.z;
    int rowBase = blockIdx.y * 64, colBase = blockIdx.x * 64;
    const int n = z ? 24 : 8;
    const __half* Bw = z ? g_Wq116 : g_Wp116;
    const int ldb = z ? 1536 : 512;
    const uint32_t sbase = s2u(raw);

    float c[16];
#pragma unroll
    for (int i = 0; i < 16; i++) c[i] = 0.f;

#define MID_ISSUE(cc, s) do { \
        int k0 = (cc) * 64; \
        uint32_t st = sbase + (s) * 18432; \
        const __half* asrc = (k0 < 512) ? (g_det16 + (size_t)rowBase * 512 + k0) \
                                        : (g_emb16 + (size_t)rowBase * 1024 + (k0 - 512)); \
        const int astr = (k0 < 512) ? 512 : 1024; \
        _Pragma("unroll") \
        for (int i = 0; i < 2; i++) { \
            int ww = tid + i * 256; \
            int row = ww >> 3, seg = ww & 7; \
            CPA16(st + row * 144 + seg * 16, \
                  (const char*)(asrc + (size_t)row * astr) + seg * 16); \
            CPA16(st + 9216 + row * 144 + seg * 16, \
                  (const char*)(Bw + (size_t)(colBase + row) * ldb + k0) + seg * 16); \
        } \
        CPC(); \
    } while (0)

    MID_ISSUE(0, 0);
    if (n > 1) MID_ISSUE(1, 1);

    for (int cc = 0; cc < n; cc++) {
        int s = cc % 3;
        if (cc + 1 < n) { CPW(1); } else { CPW(0); }
        __syncthreads();
        if (cc + 2 < n) MID_ISSUE(cc + 2, (cc + 2) % 3);

        __half (*sA)[72] = (__half(*)[72])(raw + s * 18432);
        __half (*sB)[72] = (__half(*)[72])(raw + s * 18432 + 9216);
#pragma unroll
        for (int kk = 0; kk < 4; kk++) {
            int kb = kk * 16;
            uint32_t afr[4];
            ldm_x4(afr, &sA[wm16 + (lane & 15)][kb + ((lane >> 4) << 3)]);
            uint32_t bfr[4][2];
#pragma unroll
            for (int nt2 = 0; nt2 < 4; nt2++)
                ldm_x2(bfr[nt2], &sB[nc + nt2 * 8 + (lane & 7)][kb + (((lane >> 3) & 1) << 3)]);
#pragma unroll
            for (int nt2 = 0; nt2 < 4; nt2++)
                mma16816(c + nt2 * 4, afr, bfr[nt2]);
        }
        // hazard note: stage (cc+2)%3 was last READ at chunk cc-1; the sync above
        // (all warps past compute cc-1) makes reissue safe.
    }

    const float* bia = z ? bq1 : bp1;
    __half* outp = z ? g_q116 : g_p116;
#pragma unroll
    for (int nt2 = 0; nt2 < 4; nt2++) {
        int col = colBase + nc + nt2 * 8 + (lane & 3) * 2;
#pragma unroll
        for (int h = 0; h < 2; h++) {
            int b = rowBase + wm16 + (lane >> 2) + h * 8;
            float v0 = eluf(c[nt2 * 4 + h * 2]     + bia[col]);
            float v1 = eluf(c[nt2 * 4 + h * 2 + 1] + bia[col + 1]);
            *(__half2*)(outp + (size_t)b * 512 + col) = __floats2half2_rn(v0, v1);
        }
    }
}

// K4: heads. grid(1,16,2). 64x128 tiles, 8 chunks of 64 k, 3-stage cp.async.
// stage (27648B): sA@0 (64x72h), sB@9216 (128x72h).
__global__ __launch_bounds__(256) void kg_head(
    const float* __restrict__ bp2, const float* __restrict__ bq2,
    const float* __restrict__ eps_p, const float* __restrict__ eps_q,
    float* __restrict__ out_t, float* __restrict__ stoc_out)
{
    extern __shared__ __align__(16) unsigned char raw[];
    const int tid = threadIdx.x, lane = tid & 31, w = tid >> 5;
    const int wm16 = (w & 3) * 16, wn = w >> 2;      // wn in {0,1}: 64 cols each
    int z = blockIdx.z;
    int rowBase = blockIdx.y * 64;
    const __half* A  = z ? g_q116  : g_p116;
    const __half* Bw = z ? g_Wq216 : g_Wp216;
    const uint32_t sbase = s2u(raw);

    float c[32];
#pragma unroll
    for (int i = 0; i < 32; i++) c[i] = 0.f;

#define HEAD_ISSUE(cc, s) do { \
        int k0 = (cc) * 64; \
        uint32_t st = sbase + (s) * 27648; \
        _Pragma("unroll") \
        for (int i = 0; i < 2; i++) { \
            int ww = tid + i * 256; \
            int row = ww >> 3, seg = ww & 7; \
            CPA16(st + row * 144 + seg * 16, \
                  (const char*)(A + (size_t)(rowBase + row) * 512 + k0) + seg * 16); \
        } \
        _Pragma("unroll") \
        for (int i = 0; i < 4; i++) { \
            int ww = tid + i * 256; \
            int row = ww >> 3, seg = ww & 7; \
            CPA16(st + 9216 + row * 144 + seg * 16, \
                  (const char*)(Bw + (size_t)row * 512 + k0) + seg * 16); \
        } \
        CPC(); \
    } while (0)

    HEAD_ISSUE(0, 0);
    HEAD_ISSUE(1, 1);

    for (int cc = 0; cc < 8; cc++) {
        int s = cc % 3;
        if (cc + 1 < 8) { CPW(1); } else { CPW(0); }
        __syncthreads();
        if (cc + 2 < 8) HEAD_ISSUE(cc + 2, (cc + 2) % 3);

        __half (*sA)[72] = (__half(*)[72])(raw + s * 27648);
        __half (*sB)[72] = (__half(*)[72])(raw + s * 27648 + 9216);
#pragma unroll
        for (int kk = 0; kk < 4; kk++) {
            int kb = kk * 16;
            uint32_t afr[4];
            ldm_x4(afr, &sA[wm16 + (lane & 15)][kb + ((lane >> 4) << 3)]);
            uint32_t bfr[8][2];
#pragma unroll
            for (int nt2 = 0; nt2 < 8; nt2++)
                ldm_x2(bfr[nt2], &sB[wn * 64 + nt2 * 8 + (lane & 7)][kb + (((lane >> 3) & 1) << 3)]);
#pragma unroll
            for (int nt2 = 0; nt2 < 8; nt2++)
                mma16816(c + nt2 * 4, afr, bfr[nt2]);
        }
    }
    __syncthreads();

    const float* b2  = z ? bq2 : bp2;
    const float* eps = z ? eps_q : eps_p;
    const int obase  = z ? (DET + 3 * STO) : DET;
    float (*Ss)[65] = (float(*)[65])(raw);

    if (wn == 1) {  // std cols 64..127
#pragma unroll
        for (int nt2 = 0; nt2 < 8; nt2++) {
#pragma unroll
            for (int h = 0; h < 2; h++) {
                int row = wm16 + (lane >> 2) + h * 8;
                int b = rowBase + row;
#pragma unroll
                for (int q = 0; q < 2; q++) {
                    int col = 64 + nt2 * 8 + (lane & 3) * 2 + q;
                    int ii = col - 64;
                    float s = softp(c[nt2 * 4 + h * 2 + q] + b2[col]) + 0.1f;
                    Ss[row][ii] = s;
                    out_t[(size_t)b * COUT + obase + STO + ii] = s;
                }
            }
        }
    }
    __syncthreads();
    if (wn == 0) {  // mean cols 0..63
#pragma unroll
        for (int nt2 = 0; nt2 < 8; nt2++) {
#pragma unroll
            for (int h = 0; h < 2; h++) {
                int row = wm16 + (lane >> 2) + h * 8;
                int b = rowBase + row;
#pragma unroll
                for (int q = 0; q < 2; q++) {
                    int ii = nt2 * 8 + (lane & 3) * 2 + q;
                    float m = c[nt2 * 4 + h * 2 + q] + b2[ii];
                    float s = Ss[row][ii];
                    float st = m + s * eps[b * STO + ii];
                    size_t base = (size_t)b * COUT + obase;
                    out_t[base + ii]           = m;
                    out_t[base + 2 * STO + ii] = st;
                    if (z) stoc_out[b * STO + ii] = st;
                }
            }
        }
    }
}

// ---------------------------------------------------------------------------
extern "C" void kernel_launch(void* const* d_in, const int* in_sizes, int n_in,
                              void* d_out, int out_size)
{
    const float* actions    = (const float*)d_in[0];
    const float* nonterm    = (const float*)d_in[1];
    const float* emb        = (const float*)d_in[2];
    const float* init_deter = (const float*)d_in[3];
    const float* init_stoc  = (const float*)d_in[4];
    const float* noise_p    = (const float*)d_in[5];
    const float* noise_q    = (const float*)d_in[6];
    const float* Wi   = (const float*)d_in[7];
    const float* bi   = (const float*)d_in[8];
    const float* W_ih = (const float*)d_in[9];
    const float* W_hh = (const float*)d_in[10];
    const float* b_ih = (const float*)d_in[11];
    const float* b_hh = (const float*)d_in[12];
    const float* Wp1  = (const float*)d_in[13];
    const float* bp1  = (const float*)d_in[14];
    const float* Wp2  = (const float*)d_in[15];
    const float* bp2  = (const float*)d_in[16];
    const float* Wq1  = (const float*)d_in[17];
    const float* bq1  = (const float*)d_in[18];
    const float* Wq2  = (const float*)d_in[19];
    const float* bq2  = (const float*)d_in[20];
    float* out = (float*)d_out;

    __half *wi16, *wg16, *wp116, *wq116, *wp216, *wq216;
    float  *deterBuf, *stocBuf;
    cudaGetSymbolAddress((void**)&wi16,  g_Wi16);
    cudaGetSymbolAddress((void**)&wg16,  g_Wg16);
    cudaGetSymbolAddress((void**)&wp116, g_Wp116);
    cudaGetSymbolAddress((void**)&wq116, g_Wq116);
    cudaGetSymbolAddress((void**)&wp216, g_Wp216);
    cudaGetSymbolAddress((void**)&wq216, g_Wq216);
    cudaGetSymbolAddress((void**)&deterBuf, g_deter);
    cudaGetSymbolAddress((void**)&stocBuf,  g_stoc);

    // idempotent attribute opt-ins (called every invocation — no static guards)
    cudaFuncSetAttribute(kg_gruf, cudaFuncAttributeMaxDynamicSharedMemorySize, 3 * 40960);
    cudaFuncSetAttribute(kg_mid,  cudaFuncAttributeMaxDynamicSharedMemorySize, 3 * 18432);
    cudaFuncSetAttribute(kg_head, cudaFuncAttributeMaxDynamicSharedMemorySize, 3 * 27648);

    auto prep = [&](const float* src, __half* dst, int N, int srcK, int dstK, int srcN, int trans) {
        int total = N * dstK;
        k_prep<<<(total + 255) / 256, 256>>>(src, dst, total, srcK, dstK, srcN, trans);
    };
    prep(Wi,  wi16,  512, 70,   128,  512, 1);
    prep(Wp1, wp116, 512, 512,  512,  512, 1);
    prep(Wq1, wq116, 512, 1536, 1536, 512, 1);
    prep(Wp2, wp216, 128, 512,  512,  128, 1);
    prep(Wq2, wq216, 128, 512,  512,  128, 1);
    k_prep_gru<<<1024, 256>>>(W_ih, W_hh, wg16);

    for (int t = 0; t < TT; t++) {
        const float* stoc_in  = t ? stocBuf  + ((t + 1) & 1) * BBATCH * STO : init_stoc;
        const float* deter_in = t ? deterBuf + ((t + 1) & 1) * BBATCH * DET : init_deter;
        float* deter_out = deterBuf + (t & 1) * BBATCH * DET;
        float* stoc_out  = stocBuf  + (t & 1) * BBATCH * STO;
        const float* nt_t  = nonterm + (size_t)t * BBATCH;
        const float* act_t = actions + (size_t)t * BBATCH * ACTD;
        const float* emb_t = emb     + (size_t)t * BBATCH * EMBD;
        float* out_t = out + (size_t)t * BBATCH * COUT;

        kg_x   <<<dim3(8, 16), 256>>>(stoc_in, act_t, nt_t, bi, emb_t);
        kg_gruf<<<dim3(8, 16), 256, 3 * 40960>>>(deter_in, nt_t, b_ih, b_hh,
                                                 deter_out, out_t);
        kg_mid <<<dim3(8, 16, 2), 256, 3 * 18432>>>(bp1, bq1);
        kg_head<<<dim3(1, 16, 2), 256, 3 * 27648>>>(bp2, bq2,
                                                    noise_p + (size_t)t * BBATCH * STO,
                                                    noise_q + (size_t)t * BBATCH * STO,
                                                    out_t, stoc_out);
    }
}

// round 14
// speedup vs baseline: 1.5721x; 1.5721x over previous
#include <cuda_runtime.h>
#include <cuda_fp16.h>
#include <math.h>
#include <stdint.h>

#define TT     64
#define BBATCH 1024
#define DET    512
#define STO    64
#define EMBD   1024
#define ACTD   6
#define MLPD   512
#define COUT   896

// ---------------- persistent scratch ----------------------------------------
__device__ __align__(16) __half g_Wi16 [512 * 128];
__device__ __align__(16) __half g_Wg16 [2 * 1536 * 512];   // gate-interleaved W_ih|W_hh
__device__ __align__(16) __half g_Wp116[512 * 512];
__device__ __align__(16) __half g_Wq116[512 * 1536];
__device__ __align__(16) __half g_Wp216[128 * 512];
__device__ __align__(16) __half g_Wq216[128 * 512];
__device__ __align__(16) __half g_x16  [BBATCH * 512];
__device__ __align__(16) __half g_det16[BBATCH * 512];
__device__ __align__(16) __half g_p116 [BBATCH * 512];
__device__ __align__(16) __half g_q116 [BBATCH * 512];
__device__ __align__(16) float  g_deter[2 * BBATCH * 512];
__device__ __align__(16) float  g_stoc [2 * BBATCH * 64];

// ---------------- math ------------------------------------------------------
__device__ __forceinline__ float eluf(float x)  { return x > 0.f ? x : expm1f(x); }
__device__ __forceinline__ float sigm(float x)  { return 1.f / (1.f + expf(-x)); }
__device__ __forceinline__ float softp(float x) { return x > 0.f ? x + log1pf(expf(-x)) : log1pf(expf(x)); }

// ---------------- MMA primitives --------------------------------------------
__device__ __forceinline__ void ldm_x4(uint32_t* r, const void* p) {
    uint32_t a;
    asm("{ .reg .u64 t; cvta.to.shared.u64 t, %1; cvt.u32.u64 %0, t; }" : "=r"(a) : "l"(p));
    asm volatile("ldmatrix.sync.aligned.m8n8.x4.shared.b16 {%0,%1,%2,%3}, [%4];"
                 : "=r"(r[0]), "=r"(r[1]), "=r"(r[2]), "=r"(r[3]) : "r"(a));
}
__device__ __forceinline__ void ldm_x2(uint32_t* r, const void* p) {
    uint32_t a;
    asm("{ .reg .u64 t; cvta.to.shared.u64 t, %1; cvt.u32.u64 %0, t; }" : "=r"(a) : "l"(p));
    asm volatile("ldmatrix.sync.aligned.m8n8.x2.shared.b16 {%0,%1}, [%2];"
                 : "=r"(r[0]), "=r"(r[1]) : "r"(a));
}
__device__ __forceinline__ void mma16816(float* c, const uint32_t* a, const uint32_t* b) {
    asm volatile(
        "mma.sync.aligned.m16n8k16.row.col.f32.f16.f16.f32 "
        "{%0,%1,%2,%3}, {%4,%5,%6,%7}, {%8,%9}, {%0,%1,%2,%3};"
        : "+f"(c[0]), "+f"(c[1]), "+f"(c[2]), "+f"(c[3])
        : "r"(a[0]), "r"(a[1]), "r"(a[2]), "r"(a[3]), "r"(b[0]), "r"(b[1]));
}

// ---------------- A-tile sources --------------------------------------------
#define SRC_F16    0
#define SRC_INPUT  2
#define SRC_CONCAT 3

// ---- generic C[MROWS x NCOLS] = A[MROWSxK] * B[NCOLS x K]^T ----------------
// 8 warps: WMW m-tiles of 16 rows (WMW=MROWS/16), WNW=8/WMW n-groups.
template<int MROWS, int NCOLS, int ASRC>
__device__ __forceinline__ void gemm_core(
    int kchunks,
    const __half* Af16, int lda,
    const float* Aa, const float* Ab, const float* nt,
    const __half* Bw, int ldb,
    int rowBase, int colBase,
    unsigned char* raw,
    float* cacc)
{
    constexpr int AN  = MROWS / 8;
    constexpr int BN  = NCOLS / 8;
    constexpr int WMW = MROWS / 16;
    constexpr int WNW = 8 / WMW;
    constexpr int WIDTH = NCOLS / WNW;
    constexpr int NTW = WIDTH / 8;
    const int tid = threadIdx.x, lane = tid & 31, w = tid >> 5;
    const int mrow = (w % WMW) * 16;
    const int ncol = (w / WMW) * WIDTH;
    __half (*sA)[72] = (__half(*)[72])raw;
    __half (*sB)[72] = (__half(*)[72])(raw + MROWS * 72 * 2);

#pragma unroll
    for (int i = 0; i < NTW * 4; i++) cacc[i] = 0.f;

    uint32_t aA[AN], aB[BN];
    auto fetch = [&](int k0) {
#pragma unroll
        for (int i = 0; i < AN; i++) {
            int ww = tid + i * 256;
            int row = ww >> 5, kp = ww & 31;
            int b = rowBase + row;
            int k = k0 + kp * 2;
            __half2 v;
            if (ASRC == SRC_F16) {
                v = *(const __half2*)(Af16 + (size_t)b * lda + k);
            } else if (ASRC == SRC_CONCAT) {
                if (k < DET) {
                    v = *(const __half2*)(Af16 + (size_t)b * DET + k);
                } else {
                    float2 f = *(const float2*)(Aa + (size_t)b * EMBD + (k - DET));
                    v = __floats2half2_rn(f.x, f.y);
                }
            } else { // SRC_INPUT
                float s = nt[b];
                float lo = (k < STO) ? Aa[b * STO + k] * s
                         : ((k < STO + ACTD) ? Ab[b * ACTD + (k - STO)] : 0.f);
                int k1 = k + 1;
                float hi = (k1 < STO) ? Aa[b * STO + k1] * s
                         : ((k1 < STO + ACTD) ? Ab[b * ACTD + (k1 - STO)] : 0.f);
                v = __floats2half2_rn(lo, hi);
            }
            aA[i] = *(uint32_t*)&v;
        }
#pragma unroll
        for (int i = 0; i < BN; i++) {
            int ww = tid + i * 256;
            int row = ww >> 5, kp = ww & 31;
            __half2 v = *(const __half2*)(Bw + (size_t)(colBase + row) * ldb + k0 + kp * 2);
            aB[i] = *(uint32_t*)&v;
        }
    };

    fetch(0);
    for (int c = 0; c < kchunks; c++) {
#pragma unroll
        for (int i = 0; i < AN; i++) {
            int ww = tid + i * 256;
            *(uint32_t*)&sA[ww >> 5][(ww & 31) * 2] = aA[i];
        }
#pragma unroll
        for (int i = 0; i < BN; i++) {
            int ww = tid + i * 256;
            *(uint32_t*)&sB[ww >> 5][(ww & 31) * 2] = aB[i];
        }
        __syncthreads();
#pragma unroll
        for (int kk = 0; kk < 4; kk++) {
            int kb = kk * 16;
            uint32_t afr[4];
            ldm_x4(afr, &sA[mrow + (lane & 15)][kb + ((lane >> 4) << 3)]);
            uint32_t bfr[NTW][2];
#pragma unroll
            for (int nt2 = 0; nt2 < NTW; nt2++)
                ldm_x2(bfr[nt2], &sB[ncol + nt2 * 8 + (lane & 7)][kb + (((lane >> 3) & 1) << 3)]);
#pragma unroll
            for (int nt2 = 0; nt2 < NTW; nt2++)
                mma16816(cacc + nt2 * 4, afr, bfr[nt2]);
        }
        if (c + 1 < kchunks) fetch((c + 1) * 64);
        __syncthreads();
    }
}

#define FROW(wm16, lane, h) ((wm16) + ((lane) >> 2) + ((h) ? 8 : 0))

// ---------------- prep kernels ----------------------------------------------
__global__ __launch_bounds__(256) void k_prep(
    const float* __restrict__ src, __half* __restrict__ dst,
    int total, int srcK, int dstK, int srcN, int trans)
{
    for (int idx = blockIdx.x * 256 + threadIdx.x; idx < total; idx += gridDim.x * 256) {
        int n = idx / dstK, k = idx % dstK;
        float v = 0.f;
        if (k < srcK)
            v = trans ? src[(size_t)k * srcN + n] : src[(size_t)n * srcK + k];
        dst[idx] = __float2half(v);
    }
}

__global__ __launch_bounds__(256) void k_prep_gru(
    const float* __restrict__ Wih, const float* __restrict__ Whh,
    __half* __restrict__ dst)
{
    int total = 1536 * 512;
    for (int idx = blockIdx.x * 256 + threadIdx.x; idx < total; idx += gridDim.x * 256) {
        int rr = idx / 512, k = idx % 512;
        int jb = rr / 192, rem = rr % 192;
        int gate = rem >> 6, jj = rem & 63;
        int srow = gate * 512 + jb * 64 + jj;
        dst[idx]         = __float2half(Wih[(size_t)srow * 512 + k]);
        dst[total + idx] = __float2half(Whh[(size_t)srow * 512 + k]);
    }
}

// ---------------- step kernels ----------------------------------------------

// K1: x16 = fp16(ELU(cat(stoc*nt, act) @ Wi + bi))   grid(8,16), 64-row tiles
__global__ __launch_bounds__(256) void kg_x(
    const float* __restrict__ stoc_in, const float* __restrict__ act_t,
    const float* __restrict__ nt, const float* __restrict__ bi)
{
    __shared__ __align__(16) unsigned char raw[64 * 72 * 2 + 64 * 72 * 2];
    int rowBase = blockIdx.y * 64, colBase = blockIdx.x * 64;
    float c[16];
    gemm_core<64, 64, SRC_INPUT>(2, nullptr, 0, stoc_in, act_t, nt,
                                 g_Wi16, 128, rowBase, colBase, raw, c);
    int lane = threadIdx.x & 31, w = threadIdx.x >> 5;
    int wm16 = (w & 3) * 16, nc = (w >> 2) * 32;
#pragma unroll
    for (int nt2 = 0; nt2 < 4; nt2++) {
        int col = colBase + nc + nt2 * 8 + (lane & 3) * 2;
#pragma unroll
        for (int h = 0; h < 2; h++) {
            int b = rowBase + FROW(wm16, lane, h);
            float v0 = eluf(c[nt2 * 4 + h * 2]     + bi[col]);
            float v1 = eluf(c[nt2 * 4 + h * 2 + 1] + bi[col + 1]);
            *(__half2*)(g_x16 + (size_t)b * 512 + col) = __floats2half2_rn(v0, v1);
        }
    }
}

// K2: fused GRU (R7 version). grid(8,16). 64-row x 192-col tiles.
__global__ __launch_bounds__(256) void kg_gruf(
    const float* __restrict__ deter_in, const float* __restrict__ nt,
    const float* __restrict__ b_ih, const float* __restrict__ b_hh,
    float* __restrict__ deter_out, float* __restrict__ out_t)
{
    __shared__ __align__(16) unsigned char raw[40960];
    __half (*sAx)[40]  = (__half(*)[40])(raw);
    __half (*sAh)[40]  = (__half(*)[40])(raw + 5120);
    __half (*sBi)[40]  = (__half(*)[40])(raw + 10240);
    __half (*sBh)[40]  = (__half(*)[40])(raw + 10240 + 15360);

    const int tid = threadIdx.x, lane = tid & 31, w = tid >> 5;
    const int wm16 = (w & 3) * 16, wn = w >> 2;           // wn in {0,1}: 96 cols
    const int rowBase = blockIdx.y * 64;
    const int cb192 = blockIdx.x * 192;
    const int jb64  = blockIdx.x * 64;

    float cgi[48], cgh[48];
#pragma unroll
    for (int i = 0; i < 48; i++) { cgi[i] = 0.f; cgh[i] = 0.f; }

    const __half* Bih = g_Wg16;
    const __half* Bhh = g_Wg16 + 1536 * 512;

    for (int c = 0; c < 16; c++) {
        int k0 = c * 32;
#pragma unroll
        for (int i = 0; i < 4; i++) {
            int ww = tid + i * 256;
            int row = ww >> 4, kp = ww & 15;
            int b = rowBase + row, k = k0 + kp * 2;
            *(uint32_t*)&sAx[row][kp * 2] =
                *(const uint32_t*)(g_x16 + (size_t)b * 512 + k);
            float2 f = *(const float2*)(deter_in + (size_t)b * DET + k);
            float s = nt[b];
            __half2 v = __floats2half2_rn(f.x * s, f.y * s);
            *(uint32_t*)&sAh[row][kp * 2] = *(uint32_t*)&v;
        }
#pragma unroll
        for (int i = 0; i < 12; i++) {
            int ww = tid + i * 256;
            int row = ww >> 4, kp = ww & 15;
            int k = k0 + kp * 2;
            *(uint32_t*)&sBi[row][kp * 2] =
                *(const uint32_t*)(Bih + (size_t)(cb192 + row) * 512 + k);
            *(uint32_t*)&sBh[row][kp * 2] =
                *(const uint32_t*)(Bhh + (size_t)(cb192 + row) * 512 + k);
        }
        __syncthreads();
#pragma unroll
        for (int kk = 0; kk < 2; kk++) {
            int kb = kk * 16;
            uint32_t afx[4], afh[4];
            ldm_x4(afx, &sAx[wm16 + (lane & 15)][kb + ((lane >> 4) << 3)]);
            ldm_x4(afh, &sAh[wm16 + (lane & 15)][kb + ((lane >> 4) << 3)]);
#pragma unroll
            for (int nt2 = 0; nt2 < 12; nt2++) {
                uint32_t bf[2];
                ldm_x2(bf, &sBi[wn * 96 + nt2 * 8 + (lane & 7)][kb + (((lane >> 3) & 1) << 3)]);
                mma16816(cgi + nt2 * 4, afx, bf);
                ldm_x2(bf, &sBh[wn * 96 + nt2 * 8 + (lane & 7)][kb + (((lane >> 3) & 1) << 3)]);
                mma16816(cgh + nt2 * 4, afh, bf);
            }
        }
        __syncthreads();
    }

    float (*rS)[65] = (float(*)[65])(raw);
    float (*zS)[65] = (float(*)[65])(raw + 64 * 65 * 4);

#pragma unroll
    for (int nt2 = 0; nt2 < 12; nt2++) {
#pragma unroll
        for (int h = 0; h < 2; h++) {
            int row = FROW(wm16, lane, h);
#pragma unroll
            for (int q = 0; q < 2; q++) {
                int col = wn * 96 + nt2 * 8 + (lane & 3) * 2 + q;
                int gate = col >> 6, jj = col & 63;
                int j = jb64 + jj;
                float gi = cgi[nt2 * 4 + h * 2 + q];
                float gh = cgh[nt2 * 4 + h * 2 + q];
                if (gate == 0)
                    rS[row][jj] = sigm(gi + gh + b_ih[j] + b_hh[j]);
                else if (gate == 1)
                    zS[row][jj] = sigm(gi + gh + b_ih[512 + j] + b_hh[512 + j]);
            }
        }
    }
    __syncthreads();
#pragma unroll
    for (int nt2 = 0; nt2 < 12; nt2++) {
#pragma unroll
        for (int h = 0; h < 2; h++) {
            int row = FROW(wm16, lane, h);
            int b = rowBase + row;
#pragma unroll
            for (int q = 0; q < 2; q++) {
                int col = wn * 96 + nt2 * 8 + (lane & 3) * 2 + q;
                int gate = col >> 6, jj = col & 63;
                if (gate == 2) {
                    int j = jb64 + jj;
                    float inn = cgi[nt2 * 4 + h * 2 + q] + b_ih[1024 + j];
                    float hn  = cgh[nt2 * 4 + h * 2 + q] + b_hh[1024 + j];
                    float r = rS[row][jj];
                    float z = zS[row][jj];
                    float n = tanhf(inn + r * hn);
                    float hv = deter_in[(size_t)b * DET + j] * nt[b];
                    float dn = (1.f - z) * n + z * hv;
                    deter_out[(size_t)b * DET + j] = dn;
                    g_det16[(size_t)b * 512 + j] = __float2half(dn);
                    out_t[(size_t)b * COUT + j] = dn;
                }
            }
        }
    }
}

// K3: mid layers. grid(8,16,2). HEAVY FIRST: z=0 -> q1 (K=1536), z=1 -> p1.
__global__ __launch_bounds__(256) void kg_mid(
    const float* __restrict__ emb_t,
    const float* __restrict__ bp1, const float* __restrict__ bq1)
{
    __shared__ __align__(16) unsigned char raw[64 * 72 * 2 + 64 * 72 * 2];
    int isq = (blockIdx.z == 0);    // heavy q1 scheduled first
    int rowBase = blockIdx.y * 64, colBase = blockIdx.x * 64;
    float c[16];
    if (isq)
        gemm_core<64, 64, SRC_CONCAT>(24, g_det16, 512, emb_t, nullptr, nullptr,
                                      g_Wq116, 1536, rowBase, colBase, raw, c);
    else
        gemm_core<64, 64, SRC_F16>(8, g_det16, 512, nullptr, nullptr, nullptr,
                                   g_Wp116, 512, rowBase, colBase, raw, c);
    const float* bia = isq ? bq1 : bp1;
    __half* outp = isq ? g_q116 : g_p116;
    int lane = threadIdx.x & 31, w = threadIdx.x >> 5;
    int wm16 = (w & 3) * 16, nc = (w >> 2) * 32;
#pragma unroll
    for (int nt2 = 0; nt2 < 4; nt2++) {
        int col = colBase + nc + nt2 * 8 + (lane & 3) * 2;
#pragma unroll
        for (int h = 0; h < 2; h++) {
            int b = rowBase + FROW(wm16, lane, h);
            float v0 = eluf(c[nt2 * 4 + h * 2]     + bia[col]);
            float v1 = eluf(c[nt2 * 4 + h * 2 + 1] + bia[col + 1]);
            *(__half2*)(outp + (size_t)b * 512 + col) = __floats2half2_rn(v0, v1);
        }
    }
}

// K4: heads, flat 64-CTA grid, 32-row tiles. bid>>5 = z (0 prior, 1 posterior).
__global__ __launch_bounds__(256) void kg_head(
    const float* __restrict__ bp2, const float* __restrict__ bq2,
    const float* __restrict__ eps_p, const float* __restrict__ eps_q,
    float* __restrict__ out_t, float* __restrict__ stoc_out)
{
    __shared__ __align__(16) unsigned char raw[32 * 72 * 2 + 128 * 72 * 2];
    int z = blockIdx.x >> 5;
    int rowBase = (blockIdx.x & 31) * 32;
    float c[16];
    if (z)
        gemm_core<32, 128, SRC_F16>(8, g_q116, 512, nullptr, nullptr, nullptr,
                                    g_Wq216, 512, rowBase, 0, raw, c);
    else
        gemm_core<32, 128, SRC_F16>(8, g_p116, 512, nullptr, nullptr, nullptr,
                                    g_Wp216, 512, rowBase, 0, raw, c);
    const float* b2  = z ? bq2 : bp2;
    const float* eps = z ? eps_q : eps_p;
    const int obase  = z ? (DET + 3 * STO) : DET;
    int lane = threadIdx.x & 31, w = threadIdx.x >> 5;
    int wm16 = (w & 1) * 16, nc = (w >> 1) * 32;

    float (*Ss)[65] = (float(*)[65])(raw);

    // pass 1: std columns (col >= 64)
#pragma unroll
    for (int nt2 = 0; nt2 < 4; nt2++) {
#pragma unroll
        for (int h = 0; h < 2; h++) {
            int row = wm16 + (lane >> 2) + h * 8;
            int b = rowBase + row;
#pragma unroll
            for (int q = 0; q < 2; q++) {
                int col = nc + nt2 * 8 + (lane & 3) * 2 + q;
                if (col >= 64) {
                    int ii = col - 64;
                    float s = softp(c[nt2 * 4 + h * 2 + q] + b2[col]) + 0.1f;
                    Ss[row][ii] = s;
                    out_t[(size_t)b * COUT + obase + STO + ii] = s;
                }
            }
        }
    }
    __syncthreads();
    // pass 2: mean columns + sample
#pragma unroll
    for (int nt2 = 0; nt2 < 4; nt2++) {
#pragma unroll
        for (int h = 0; h < 2; h++) {
            int row = wm16 + (lane >> 2) + h * 8;
            int b = rowBase + row;
#pragma unroll
            for (int q = 0; q < 2; q++) {
                int col = nc + nt2 * 8 + (lane & 3) * 2 + q;
                if (col < 64) {
                    float m = c[nt2 * 4 + h * 2 + q] + b2[col];
                    float s = Ss[row][col];
                    float st = m + s * eps[b * STO + col];
                    size_t base = (size_t)b * COUT + obase;
                    out_t[base + col]           = m;
                    out_t[base + 2 * STO + col] = st;
                    if (z) stoc_out[b * STO + col] = st;
                }
            }
        }
    }
}

// ---------------------------------------------------------------------------
extern "C" void kernel_launch(void* const* d_in, const int* in_sizes, int n_in,
                              void* d_out, int out_size)
{
    const float* actions    = (const float*)d_in[0];
    const float* nonterm    = (const float*)d_in[1];
    const float* emb        = (const float*)d_in[2];
    const float* init_deter = (const float*)d_in[3];
    const float* init_stoc  = (const float*)d_in[4];
    const float* noise_p    = (const float*)d_in[5];
    const float* noise_q    = (const float*)d_in[6];
    const float* Wi   = (const float*)d_in[7];
    const float* bi   = (const float*)d_in[8];
    const float* W_ih = (const float*)d_in[9];
    const float* W_hh = (const float*)d_in[10];
    const float* b_ih = (const float*)d_in[11];
    const float* b_hh = (const float*)d_in[12];
    const float* Wp1  = (const float*)d_in[13];
    const float* bp1  = (const float*)d_in[14];
    const float* Wp2  = (const float*)d_in[15];
    const float* bp2  = (const float*)d_in[16];
    const float* Wq1  = (const float*)d_in[17];
    const float* bq1  = (const float*)d_in[18];
    const float* Wq2  = (const float*)d_in[19];
    const float* bq2  = (const float*)d_in[20];
    float* out = (float*)d_out;

    __half *wi16, *wg16, *wp116, *wq116, *wp216, *wq216;
    float  *deterBuf, *stocBuf;
    cudaGetSymbolAddress((void**)&wi16,  g_Wi16);
    cudaGetSymbolAddress((void**)&wg16,  g_Wg16);
    cudaGetSymbolAddress((void**)&wp116, g_Wp116);
    cudaGetSymbolAddress((void**)&wq116, g_Wq116);
    cudaGetSymbolAddress((void**)&wp216, g_Wp216);
    cudaGetSymbolAddress((void**)&wq216, g_Wq216);
    cudaGetSymbolAddress((void**)&deterBuf, g_deter);
    cudaGetSymbolAddress((void**)&stocBuf,  g_stoc);

    auto prep = [&](const float* src, __half* dst, int N, int srcK, int dstK, int srcN, int trans) {
        int total = N * dstK;
        k_prep<<<(total + 255) / 256, 256>>>(src, dst, total, srcK, dstK, srcN, trans);
    };
    prep(Wi,  wi16,  512, 70,   128,  512, 1);
    prep(Wp1, wp116, 512, 512,  512,  512, 1);
    prep(Wq1, wq116, 512, 1536, 1536, 512, 1);
    prep(Wp2, wp216, 128, 512,  512,  128, 1);
    prep(Wq2, wq216, 128, 512,  512,  128, 1);
    k_prep_gru<<<1024, 256>>>(W_ih, W_hh, wg16);

    for (int t = 0; t < TT; t++) {
        const float* stoc_in  = t ? stocBuf  + ((t + 1) & 1) * BBATCH * STO : init_stoc;
        const float* deter_in = t ? deterBuf + ((t + 1) & 1) * BBATCH * DET : init_deter;
        float* deter_out = deterBuf + (t & 1) * BBATCH * DET;
        float* stoc_out  = stocBuf  + (t & 1) * BBATCH * STO;
        const float* nt_t  = nonterm + (size_t)t * BBATCH;
        const float* act_t = actions + (size_t)t * BBATCH * ACTD;
        const float* emb_t = emb     + (size_t)t * BBATCH * EMBD;
        float* out_t = out + (size_t)t * BBATCH * COUT;

        kg_x   <<<dim3(8, 16), 256>>>(stoc_in, act_t, nt_t, bi);
        kg_gruf<<<dim3(8, 16), 256>>>(deter_in, nt_t, b_ih, b_hh,
                                      deter_out, out_t);
        kg_mid <<<dim3(8, 16, 2), 256>>>(emb_t, bp1, bq1);
        kg_head<<<64, 256>>>(bp2, bq2,
                             noise_p + (size_t)t * BBATCH * STO,
                             noise_q + (size_t)t * BBATCH * STO,
                             out_t, stoc_out);
    }
}